// round 10
// baseline (speedup 1.0000x reference)
#include <cuda_runtime.h>

#define BATCH   128
#define NANCH   8732
#define NCLS    21
#define NLOG    25
#define MAXOUT  5
#define CONF    0.5f
#define DEC_T   128                        // threads per block
#define TILE_A  128                        // anchors per tile
#define TILE_F4 800                        // float4 per tile (128*25/4)
#define NTILE   8732                       // total tiles (BATCH*NANCH/TILE_A)
#define PBLK    1184                       // persistent blocks (148 SM * 8)
#define CSTRIDE 32                         // counter pad: 128 B
#define SCAP    448                        // smem-staged candidate cap
#define RCAP    2048                       // register-bitmask cap

typedef unsigned int       u32;
typedef unsigned long long u64;

__device__ int    g_cnt[BATCH * CSTRIDE];
__device__ int    g_done[BATCH * CSTRIDE];
__device__ float4 g_cbox[BATCH * NANCH];
__device__ u64    g_ckey[BATCH * NANCH];
__device__ float  g_ccls[BATCH * NANCH];

__device__ __forceinline__ void cp16(u32 s, const void* g) {
    asm volatile("cp.async.cg.shared.global [%0], [%1], 16;" :: "r"(s), "l"(g));
}
__device__ __forceinline__ void cp_commit() {
    asm volatile("cp.async.commit_group;");
}
template <int N>
__device__ __forceinline__ void cp_wait() {
    asm volatile("cp.async.wait_group %0;" :: "n"(N));
}

// ---------------------------------------------------------------------------
// NMS for one batch (R8-proven: no stores in loop, register survivor bitmask).
// ---------------------------------------------------------------------------
__device__ void do_nms(int b, char* sh, float* __restrict__ out, int tid) {
    __threadfence();                                   // acquire
    int M = g_cnt[b * CSTRIDE];
    size_t base = (size_t)b * NANCH;

    u64*    skey = (u64*)sh;
    float4* sbox = (float4*)(sh + SCAP * 8);

    bool fits = (M <= SCAP);
    if (fits) {
        for (int i = tid; i < M; i += DEC_T) {
            skey[i] = g_ckey[base + i];
            sbox[i] = g_cbox[base + i];
        }
    }
    __syncthreads();

    if (tid < 32) {
        float* ob = out + (size_t)b * MAXOUT * 6;
        if (M <= RCAP) {
            const u64*    __restrict__ keys  = fits ? skey : (g_ckey + base);
            const float4* __restrict__ boxes = fits ? sbox : (g_cbox + base);
            u64 alive = ~0ull;
            u64 bp = 0ull;
            for (int i = tid; i < M; i += 32) {
                u64 k = keys[i];
                if (k > bp) bp = k;
            }
#pragma unroll
            for (int off = 16; off > 0; off >>= 1) {
                u64 o = __shfl_xor_sync(0xffffffffu, bp, off);
                if (o > bp) bp = o;
            }
            for (int t = 0; t < MAXOUT; t++) {
                if (bp == 0ull) {
                    if (tid == 0)
                        for (int tt = t; tt < MAXOUT; tt++) {
                            float* o = ob + tt * 6;
                            o[0]=o[1]=o[2]=o[3]=o[4]=o[5]=0.f;
                        }
                    break;
                }
                int   pos = (int)(bp & 0x3FFFull);
                float sc  = __uint_as_float((u32)(bp >> 32) & 0x7FFFFFFFu);
                float4 B  = boxes[pos];
                if (tid == 0) {
                    float* o = ob + t * 6;
                    o[0]=B.x; o[1]=B.y; o[2]=B.z; o[3]=B.w;
                    o[4]=g_ccls[base + pos]; o[5]=sc;
                }
                if (t == MAXOUT - 1) break;
                float a1 = (B.z - B.x) * (B.w - B.y);
                bp = 0ull;
                int kk = 0;
                for (int i = tid; i < M; i += 32, kk++) {
                    if (!((alive >> kk) & 1ull)) continue;
                    float4 C = boxes[i];
                    float ty  = fmaxf(B.x, C.x);
                    float tx  = fmaxf(B.y, C.y);
                    float by  = fminf(B.z, C.z);
                    float bxr = fminf(B.w, C.w);
                    float hh  = fmaxf(by - ty, 0.f);
                    float ww  = fmaxf(bxr - tx, 0.f);
                    float inter = hh * ww;
                    float a2 = (C.z - C.x) * (C.w - C.y);
                    float iou = inter / (a1 + a2 - inter + 1e-12f);
                    if (iou > 0.5f) alive &= ~(1ull << kk);
                    else {
                        u64 k = keys[i];
                        if (k > bp) bp = k;
                    }
                }
#pragma unroll
                for (int off = 16; off > 0; off >>= 1) {
                    u64 o = __shfl_xor_sync(0xffffffffu, bp, off);
                    if (o > bp) bp = o;
                }
            }
        } else {
            // destructive fallback (never expected at these sizes)
            u64* kg = g_ckey + base;
            const float4* boxes = g_cbox + base;
            u64 bp = 0ull;
            for (int i = tid; i < M; i += 32) {
                u64 k = kg[i];
                if (k > bp) bp = k;
            }
#pragma unroll
            for (int off = 16; off > 0; off >>= 1) {
                u64 o = __shfl_xor_sync(0xffffffffu, bp, off);
                if (o > bp) bp = o;
            }
            for (int t = 0; t < MAXOUT; t++) {
                if (bp == 0ull) {
                    if (tid == 0)
                        for (int tt = t; tt < MAXOUT; tt++) {
                            float* o = ob + tt * 6;
                            o[0]=o[1]=o[2]=o[3]=o[4]=o[5]=0.f;
                        }
                    break;
                }
                int   pos = (int)(bp & 0x3FFFull);
                float sc  = __uint_as_float((u32)(bp >> 32) & 0x7FFFFFFFu);
                float4 B  = boxes[pos];
                if (tid == 0) {
                    float* o = ob + t * 6;
                    o[0]=B.x; o[1]=B.y; o[2]=B.z; o[3]=B.w;
                    o[4]=g_ccls[base + pos]; o[5]=sc;
                }
                if (t == MAXOUT - 1) break;
                float a1 = (B.z - B.x) * (B.w - B.y);
                bp = 0ull;
                for (int i = tid; i < M; i += 32) {
                    u64 k = kg[i];
                    if (!k) continue;
                    float4 C = boxes[i];
                    float ty  = fmaxf(B.x, C.x);
                    float tx  = fmaxf(B.y, C.y);
                    float by  = fminf(B.z, C.z);
                    float bxr = fminf(B.w, C.w);
                    float hh  = fmaxf(by - ty, 0.f);
                    float ww  = fmaxf(bxr - tx, 0.f);
                    float inter = hh * ww;
                    float a2 = (C.z - C.x) * (C.w - C.y);
                    float iou = inter / (a1 + a2 - inter + 1e-12f);
                    if (iou > 0.5f) kg[i] = 0ull;
                    else if (k > bp) bp = k;
                }
#pragma unroll
                for (int off = 16; off > 0; off >>= 1) {
                    u64 o = __shfl_xor_sync(0xffffffffu, bp, off);
                    if (o > bp) bp = o;
                }
            }
        }
    }
    __syncthreads();
    if (tid == 0) {                                    // reset for next replay
        g_cnt[b * CSTRIDE]  = 0;
        g_done[b * CSTRIDE] = 0;
    }
    __syncthreads();
}

// ---------------------------------------------------------------------------
// Persistent fused kernel: double-buffered cp.async decode pipeline +
// deferred last-block-per-batch NMS.
// ---------------------------------------------------------------------------
__global__ void __launch_bounds__(DEC_T)
fused_kernel(const float* __restrict__ logits, const float* __restrict__ db,
             float* __restrict__ out) {
    __shared__ __align__(16) float buf[2][TILE_A * NLOG];  // 2 x 12.8 KB
    __shared__ int s_pend[20];
    __shared__ int s_np;

    int tid = threadIdx.x;
    int bid = blockIdx.x;
    if (tid == 0) s_np = 0;

    int ntiles = (NTILE - bid + PBLK - 1) / PBLK;          // tiles: bid + i*PBLK
    if (ntiles > 0) {
        // prologue: prefetch first tile into buf[0]
        {
            const float4* src = (const float4*)logits + (size_t)bid * TILE_F4;
            u32 sb = (u32)__cvta_generic_to_shared(buf[0]);
#pragma unroll
            for (int k = 0; k < 7; k++) {
                int i = tid + k * DEC_T;
                if (i < TILE_F4) cp16(sb + i * 16, src + i);
            }
            cp_commit();
        }

        for (int it = 0; it < ntiles; it++) {
            int t = bid + it * PBLK;
            // prefetch next tile
            if (it + 1 < ntiles) {
                int tn = t + PBLK;
                const float4* src = (const float4*)logits + (size_t)tn * TILE_F4;
                u32 sb = (u32)__cvta_generic_to_shared(buf[(it + 1) & 1]);
#pragma unroll
                for (int k = 0; k < 7; k++) {
                    int i = tid + k * DEC_T;
                    if (i < TILE_F4) cp16(sb + i * 16, src + i);
                }
                cp_commit();
                cp_wait<1>();
            } else {
                cp_wait<0>();
            }
            __syncthreads();               // tile t resident for all threads

            const float* L = buf[it & 1] + tid * NLOG;
            int gid = t * TILE_A + tid;

            float best = L[4];
            int   bi   = 0;
#pragma unroll
            for (int c = 1; c < NCLS; c++) {
                float vv = L[4 + c];
                if (vv > best) { best = vv; bi = c; }
            }
            float sum = 0.f;
#pragma unroll
            for (int c = 0; c < NCLS; c++) sum += __expf(L[4 + c] - best);
            float score = 1.0f / sum;

            if (bi != 0 && score > CONF) {
                int b = gid / NANCH;
                int n = gid % NANCH;
                float4 d = ((const float4*)db)[n];
                float cy = 0.5f * (d.z + d.x);
                float cx = 0.5f * (d.w + d.y);
                float h  = d.z - d.x;
                float w  = d.w - d.y;
                float ncy = L[0] * h + cy;
                float ncx = L[1] * w + cx;
                float nh  = __expf(L[2]) * h;
                float nw  = __expf(L[3]) * w;
                float4 box;
                box.x = fminf(fmaxf(ncy - 0.5f * nh, 0.f), 1.f);
                box.y = fminf(fmaxf(ncx - 0.5f * nw, 0.f), 1.f);
                box.z = fminf(fmaxf(ncy + 0.5f * nh, 0.f), 1.f);
                box.w = fminf(fmaxf(ncx + 0.5f * nw, 0.f), 1.f);

                int slot = atomicAdd(&g_cnt[b * CSTRIDE], 1);
                size_t o = (size_t)b * NANCH + slot;
                u32 hi = __float_as_uint(score) | 0x80000000u;
                u32 lo = ((u32)(NANCH - n) << 14) | (u32)slot;
                g_ckey[o] = ((u64)hi << 32) | lo;
                g_cbox[o] = box;
                g_ccls[o] = (float)bi;
            }

            __syncthreads();               // stores done; buffer reusable
            if (tid == 0) {
                __threadfence();           // cumulative release of tile writes
                long long a0 = (long long)t * TILE_A;
                int b0 = (int)(a0 / NANCH);
                int b1 = (int)((a0 + TILE_A - 1) / NANCH);
                int p = atomicAdd(&g_done[b0 * CSTRIDE], 1);
                int e = ((b0 + 1) * NANCH - 1) / TILE_A - (b0 * NANCH) / TILE_A + 1;
                if (p == e - 1) s_pend[atomicAdd(&s_np, 1)] = b0;
                if (b1 != b0) {
                    p = atomicAdd(&g_done[b1 * CSTRIDE], 1);
                    e = ((b1 + 1) * NANCH - 1) / TILE_A - (b1 * NANCH) / TILE_A + 1;
                    if (p == e - 1) s_pend[atomicAdd(&s_np, 1)] = b1;
                }
            }
        }
    }

    // ---- deferred NMS for batches this block completed ----
    __syncthreads();
    int np = s_np;
    for (int j = 0; j < np; j++)
        do_nms(s_pend[j], (char*)buf, out, tid);
}

// ---------------------------------------------------------------------------
extern "C" void kernel_launch(void* const* d_in, const int* in_sizes, int n_in,
                              void* d_out, int out_size) {
    const float* logits = (const float*)d_in[0];   // [128, 8732, 25]
    const float* db     = (const float*)d_in[1];   // [8732, 4]
    float*       out    = (float*)d_out;           // [128, 5, 6]

    fused_kernel<<<PBLK, DEC_T>>>(logits, db, out);
}

// round 11
// speedup vs baseline: 2.0414x; 2.0414x over previous
#include <cuda_runtime.h>

#define BATCH   128
#define NANCH   8732
#define NCLS    21
#define NLOG    25
#define MAXOUT  5
#define CONF    0.5f
#define DEC_T   128
#define NMS_T   256
#define CSTRIDE 32                         // counter pad: 128 B
#define SCAP    448                        // smem-staged candidate cap
#define RCAP    2048                       // register-bitmask cap

typedef unsigned int       u32;
typedef unsigned long long u64;

__device__ int    g_cnt[BATCH * CSTRIDE];
__device__ float4 g_cbox[BATCH * NANCH];
__device__ u64    g_ckey[BATCH * NANCH];
__device__ float  g_ccls[BATCH * NANCH];

// ---------------------------------------------------------------------------
// Decode + lazy argmax + candidate compaction (R3-proven memory structure).
// Hot path: FMNMX max chain + softmax only; class index recovered by equality
// scan inside the rare candidate branch (class 0 wins ties = jnp.argmax).
// ---------------------------------------------------------------------------
__global__ void __launch_bounds__(DEC_T)
decode_kernel(const float* __restrict__ logits, const float* __restrict__ db) {
    __shared__ float tile[DEC_T * NLOG];
    const int NV = DEC_T * NLOG / 4;                       // 800 float4

    long long base = (long long)blockIdx.x * DEC_T;
    const float4* __restrict__ src = (const float4*)(logits + base * NLOG);
    float4* dst = (float4*)tile;

    float4 v[7];
    int tid = threadIdx.x;
#pragma unroll
    for (int k = 0; k < 7; k++) {
        int i = tid + k * DEC_T;
        if (i < NV) v[k] = src[i];
    }
#pragma unroll
    for (int k = 0; k < 7; k++) {
        int i = tid + k * DEC_T;
        if (i < NV) dst[i] = v[k];
    }
    __syncthreads();

    int gid = (int)base + tid;
    const float* L = tile + tid * NLOG;

    float c0 = L[4];                       // background logit
    float m1 = L[5];                       // max over classes 1..20
#pragma unroll
    for (int c = 2; c < NCLS; c++) m1 = fmaxf(m1, L[4 + c]);
    float mx = fmaxf(c0, m1);

    float sum = 0.f;
#pragma unroll
    for (int c = 0; c < NCLS; c++) sum += __expf(L[4 + c] - mx);
    float score = 1.0f / sum;

    // candidate iff argmax != 0 (m1 strictly beats c0) and score > 0.5
    if (m1 > c0 && score > CONF) {
        // first-occurrence class index among 1..20
        int bi = 1;
#pragma unroll
        for (int c = NCLS - 1; c >= 1; c--) if (L[4 + c] == m1) bi = c;

        int b = gid / NANCH;
        int n = gid % NANCH;
        float4 d = ((const float4*)db)[n];                 // y0,x0,y1,x1
        float cy = 0.5f * (d.z + d.x);
        float cx = 0.5f * (d.w + d.y);
        float h  = d.z - d.x;
        float w  = d.w - d.y;
        float ncy = L[0] * h + cy;
        float ncx = L[1] * w + cx;
        float nh  = __expf(L[2]) * h;
        float nw  = __expf(L[3]) * w;
        float4 box;
        box.x = fminf(fmaxf(ncy - 0.5f * nh, 0.f), 1.f);
        box.y = fminf(fmaxf(ncx - 0.5f * nw, 0.f), 1.f);
        box.z = fminf(fmaxf(ncy + 0.5f * nh, 0.f), 1.f);
        box.w = fminf(fmaxf(ncx + 0.5f * nw, 0.f), 1.f);

        int slot = atomicAdd(&g_cnt[b * CSTRIDE], 1);
        size_t o = (size_t)b * NANCH + slot;
        // key: [score bits|0x80000000][NANCH-n : 14b][slot : 14b]
        u32 hi = __float_as_uint(score) | 0x80000000u;
        u32 lo = ((u32)(NANCH - n) << 14) | (u32)slot;
        g_ckey[o] = ((u64)hi << 32) | lo;
        g_cbox[o] = box;
        g_ccls[o] = (float)bi;
    }
    cudaTriggerProgrammaticLaunchCompletion();
}

// ---------------------------------------------------------------------------
// NMS: 256 threads stage candidates to smem in parallel; warp 0 runs the
// select/suppress loop with NO stores in the loop body (register survivor
// bitmask) -> smem loads pipeline instead of serializing behind aliasing.
// ---------------------------------------------------------------------------
__global__ void __launch_bounds__(NMS_T)
nms_kernel(float* __restrict__ out) {
    __shared__ u64    skey[SCAP];
    __shared__ float4 sbox[SCAP];

    cudaGridDependencySynchronize();       // PDL: wait for decode results

    int b   = blockIdx.x;
    int tid = threadIdx.x;
    int M   = g_cnt[b * CSTRIDE];
    size_t base = (size_t)b * NANCH;

    bool fits = (M <= SCAP);
    if (fits) {
        for (int i = tid; i < M; i += NMS_T) {
            skey[i] = g_ckey[base + i];
            sbox[i] = g_cbox[base + i];
        }
    }
    __syncthreads();
    if (tid == 0) g_cnt[b * CSTRIDE] = 0;  // reset for next graph replay

    if (tid >= 32) return;
    float* ob = out + (size_t)b * MAXOUT * 6;

    if (M <= RCAP) {
        const u64*    __restrict__ keys  = fits ? skey : (g_ckey + base);
        const float4* __restrict__ boxes = fits ? sbox : (g_cbox + base);
        u64 alive = ~0ull;                 // bit k = element tid + 32k
        u64 bp = 0ull;
        for (int i = tid; i < M; i += 32) {
            u64 k = keys[i];
            if (k > bp) bp = k;
        }
#pragma unroll
        for (int off = 16; off > 0; off >>= 1) {
            u64 o = __shfl_xor_sync(0xffffffffu, bp, off);
            if (o > bp) bp = o;
        }
        for (int t = 0; t < MAXOUT; t++) {
            if (bp == 0ull) {
                if (tid == 0)
                    for (int tt = t; tt < MAXOUT; tt++) {
                        float* o = ob + tt * 6;
                        o[0]=o[1]=o[2]=o[3]=o[4]=o[5]=0.f;
                    }
                return;
            }
            int   pos = (int)(bp & 0x3FFFull);
            float sc  = __uint_as_float((u32)(bp >> 32) & 0x7FFFFFFFu);
            float4 B  = boxes[pos];
            if (tid == 0) {
                float* o = ob + t * 6;
                o[0]=B.x; o[1]=B.y; o[2]=B.z; o[3]=B.w;
                o[4]=g_ccls[base + pos]; o[5]=sc;
            }
            if (t == MAXOUT - 1) return;

            float a1 = (B.z - B.x) * (B.w - B.y);
            bp = 0ull;
            int kk = 0;
            for (int i = tid; i < M; i += 32, kk++) {
                if (!((alive >> kk) & 1ull)) continue;
                float4 C = boxes[i];
                float ty  = fmaxf(B.x, C.x);
                float tx  = fmaxf(B.y, C.y);
                float by  = fminf(B.z, C.z);
                float bxr = fminf(B.w, C.w);
                float hh  = fmaxf(by - ty, 0.f);
                float ww  = fmaxf(bxr - tx, 0.f);
                float inter = hh * ww;
                float a2 = (C.z - C.x) * (C.w - C.y);
                float iou = inter / (a1 + a2 - inter + 1e-12f);
                if (iou > 0.5f) alive &= ~(1ull << kk);
                else {
                    u64 k = keys[i];
                    if (k > bp) bp = k;
                }
            }
#pragma unroll
            for (int off = 16; off > 0; off >>= 1) {
                u64 o = __shfl_xor_sync(0xffffffffu, bp, off);
                if (o > bp) bp = o;
            }
        }
    } else {
        // destructive fallback (M > RCAP; never expected at these sizes)
        u64* kg = g_ckey + base;
        const float4* boxes = g_cbox + base;
        u64 bp = 0ull;
        for (int i = tid; i < M; i += 32) {
            u64 k = kg[i];
            if (k > bp) bp = k;
        }
#pragma unroll
        for (int off = 16; off > 0; off >>= 1) {
            u64 o = __shfl_xor_sync(0xffffffffu, bp, off);
            if (o > bp) bp = o;
        }
        for (int t = 0; t < MAXOUT; t++) {
            if (bp == 0ull) {
                if (tid == 0)
                    for (int tt = t; tt < MAXOUT; tt++) {
                        float* o = ob + tt * 6;
                        o[0]=o[1]=o[2]=o[3]=o[4]=o[5]=0.f;
                    }
                return;
            }
            int   pos = (int)(bp & 0x3FFFull);
            float sc  = __uint_as_float((u32)(bp >> 32) & 0x7FFFFFFFu);
            float4 B  = boxes[pos];
            if (tid == 0) {
                float* o = ob + t * 6;
                o[0]=B.x; o[1]=B.y; o[2]=B.z; o[3]=B.w;
                o[4]=g_ccls[base + pos]; o[5]=sc;
            }
            if (t == MAXOUT - 1) return;
            float a1 = (B.z - B.x) * (B.w - B.y);
            bp = 0ull;
            for (int i = tid; i < M; i += 32) {
                u64 k = kg[i];
                if (!k) continue;
                float4 C = boxes[i];
                float ty  = fmaxf(B.x, C.x);
                float tx  = fmaxf(B.y, C.y);
                float by  = fminf(B.z, C.z);
                float bxr = fminf(B.w, C.w);
                float hh  = fmaxf(by - ty, 0.f);
                float ww  = fmaxf(bxr - tx, 0.f);
                float inter = hh * ww;
                float a2 = (C.z - C.x) * (C.w - C.y);
                float iou = inter / (a1 + a2 - inter + 1e-12f);
                if (iou > 0.5f) kg[i] = 0ull;
                else if (k > bp) bp = k;
            }
#pragma unroll
            for (int off = 16; off > 0; off >>= 1) {
                u64 o = __shfl_xor_sync(0xffffffffu, bp, off);
                if (o > bp) bp = o;
            }
        }
    }
}

// ---------------------------------------------------------------------------
extern "C" void kernel_launch(void* const* d_in, const int* in_sizes, int n_in,
                              void* d_out, int out_size) {
    const float* logits = (const float*)d_in[0];   // [128, 8732, 25]
    const float* db     = (const float*)d_in[1];   // [8732, 4]
    float*       out    = (float*)d_out;           // [128, 5, 6]

    decode_kernel<<<BATCH * NANCH / DEC_T, DEC_T>>>(logits, db);

    cudaLaunchConfig_t cfg = {};
    cfg.gridDim  = dim3(BATCH);
    cfg.blockDim = dim3(NMS_T);
    cfg.dynamicSmemBytes = 0;
    cfg.stream = 0;
    cudaLaunchAttribute attr[1];
    attr[0].id = cudaLaunchAttributeProgrammaticStreamSerialization;
    attr[0].val.programmaticStreamSerializationAllowed = 1;
    cfg.attrs = attr;
    cfg.numAttrs = 1;
    cudaLaunchKernelEx(&cfg, nms_kernel, out);
}